// round 1
// baseline (speedup 1.0000x reference)
#include <cuda_runtime.h>

typedef unsigned long long u64;

#define C_IN  64
#define C_OUT 128
#define KK    27
#define HH    100000
#define BN    64
#define NBLK  ((HH + BN - 1) / BN)

// Scratch (static device globals -- allocation-free)
__device__ float g_xt[(size_t)HH * C_IN];           // [h][c]
__device__ float g_wt[KK * C_IN * C_OUT];           // [k][c][o]
__device__ int   g_is64;

// ---------------------------------------------------------------------------
// Detect whether neigh was serialized as int64 or int32 (jax x64 ambiguity).
// Valid int64 indices are in [0, HH); two random int32s read as one int64 are
// astronomically unlikely to all land in that range across 256 words.
// ---------------------------------------------------------------------------
__global__ void detect_dtype(const long long* __restrict__ n64) {
    if (threadIdx.x == 0 && blockIdx.x == 0) {
        int ok = 1;
        for (int i = 0; i < 256; i++) {
            long long v = n64[i];
            if (v < -(long long)HH || v >= (long long)HH) { ok = 0; break; }
        }
        g_is64 = ok;
    }
}

// ---------------------------------------------------------------------------
// Transpose x[c*HH + h] -> xt[h*64 + c]  (coalesced both sides via smem tile)
// ---------------------------------------------------------------------------
__global__ void transpose_x(const float* __restrict__ x) {
    __shared__ float tile[32][33];
    const int hb = blockIdx.x * 32;
    const int cb = blockIdx.y * 32;
    const int tx = threadIdx.x;   // 32
    const int ty = threadIdx.y;   // 8
    #pragma unroll
    for (int i = 0; i < 32; i += 8) {
        int c = cb + ty + i;
        int h = hb + tx;
        tile[ty + i][tx] = (h < HH) ? x[(size_t)c * HH + h] : 0.f;
    }
    __syncthreads();
    #pragma unroll
    for (int i = 0; i < 32; i += 8) {
        int h = hb + ty + i;
        int c = cb + tx;
        if (h < HH) g_xt[(size_t)h * C_IN + c] = tile[tx][ty + i];
    }
}

// ---------------------------------------------------------------------------
// Transpose W[o][c][k] -> wt[k][c][o]
// ---------------------------------------------------------------------------
__global__ void transpose_w(const float* __restrict__ w) {
    int idx = blockIdx.x * blockDim.x + threadIdx.x;
    if (idx >= C_OUT * C_IN * KK) return;
    int k = idx % KK;
    int c = (idx / KK) % C_IN;
    int o = idx / (KK * C_IN);
    g_wt[(k * C_IN + c) * C_OUT + o] = w[idx];
}

// ---------------------------------------------------------------------------
// Packed-f32 helpers (fma.rn.f32x2: 2 FMAs/instr -> 128 FMA/cyc/SM)
// ---------------------------------------------------------------------------
__device__ __forceinline__ u64 dup_f32(float v) {
    u64 r; unsigned u = __float_as_uint(v);
    asm("mov.b64 %0, {%1, %1};" : "=l"(r) : "r"(u));
    return r;
}
__device__ __forceinline__ void ffma2(u64& d, u64 a, u64 b) {
    asm("fma.rn.f32x2 %0, %1, %2, %3;" : "=l"(d) : "l"(a), "l"(b), "l"(d));
}
__device__ __forceinline__ float2 unpk(u64 v) {
    unsigned lo, hi;
    asm("mov.b64 {%0, %1}, %2;" : "=r"(lo), "=r"(hi) : "l"(v));
    return make_float2(__uint_as_float(lo), __uint_as_float(hi));
}

// ---------------------------------------------------------------------------
// Main GEMM: C[128 x HH] = W[128 x 1728] * gather(xt)[1728 x HH], fused relu.
// Block: 256 threads, tile 128(o) x 64(h). Thread tile: 8(o) x 4(h) as
// 4 o-pairs x 4 h f32x2 accumulators.
// ---------------------------------------------------------------------------
__global__ __launch_bounds__(256, 2)
void conv_gemm(const void* __restrict__ neigh_raw, float* __restrict__ out) {
    __shared__ float sW[C_IN * C_OUT];   // [c][o]  32 KB
    __shared__ float sG[C_IN][BN];       // [c][h]  16 KB

    const int tid = threadIdx.x;
    const int tx  = tid & 15;            // h group
    const int ty  = tid >> 4;            // o group
    const int o0  = ty * 8;
    const int hb  = blockIdx.x * BN;

    const int hl  = tid >> 2;            // gather: h-local 0..63
    const int seg = tid & 3;             // gather: 16-channel segment
    const int hg  = hb + hl;

    const int is64 = g_is64;
    const long long* n64 = (const long long*)neigh_raw;
    const int*       n32 = (const int*)neigh_raw;

    u64 acc[4][4];
    #pragma unroll
    for (int p = 0; p < 4; p++)
        #pragma unroll
        for (int j = 0; j < 4; j++) acc[p][j] = 0ull;

    for (int k = 0; k < KK; k++) {
        // ---- stage weight tile [64c x 128o] (coalesced) ----
        const float4* ws = (const float4*)(g_wt + k * (C_IN * C_OUT));
        float4*       wd = (float4*)sW;
        #pragma unroll
        for (int i = 0; i < 8; i++) wd[tid + 256 * i] = ws[tid + 256 * i];

        // ---- gather tile: 64 h, each 64 contiguous channels from xt ----
        long long n = -1;
        if (hg < HH) {
            long long idx = (long long)hg * KK + k;
            n = is64 ? n64[idx] : (long long)n32[idx];
        }
        if (n >= 0) {
            const float4* src = (const float4*)(g_xt + (size_t)n * C_IN + seg * 16);
            #pragma unroll
            for (int q = 0; q < 4; q++) {
                float4 v = src[q];
                int c0 = seg * 16 + q * 4;
                sG[c0 + 0][hl] = v.x;
                sG[c0 + 1][hl] = v.y;
                sG[c0 + 2][hl] = v.z;
                sG[c0 + 3][hl] = v.w;
            }
        } else {
            #pragma unroll
            for (int q = 0; q < 16; q++) sG[seg * 16 + q][hl] = 0.f;
        }
        __syncthreads();

        // ---- inner product over 64 channels ----
        #pragma unroll 8
        for (int c = 0; c < C_IN; c++) {
            ulonglong2 wv0 = *(const ulonglong2*)(sW + c * C_OUT + o0);
            ulonglong2 wv1 = *(const ulonglong2*)(sW + c * C_OUT + o0 + 4);
            float4 gv = *(const float4*)(&sG[c][tx * 4]);
            u64 b0 = dup_f32(gv.x), b1 = dup_f32(gv.y);
            u64 b2 = dup_f32(gv.z), b3 = dup_f32(gv.w);
            ffma2(acc[0][0], wv0.x, b0); ffma2(acc[0][1], wv0.x, b1);
            ffma2(acc[0][2], wv0.x, b2); ffma2(acc[0][3], wv0.x, b3);
            ffma2(acc[1][0], wv0.y, b0); ffma2(acc[1][1], wv0.y, b1);
            ffma2(acc[1][2], wv0.y, b2); ffma2(acc[1][3], wv0.y, b3);
            ffma2(acc[2][0], wv1.x, b0); ffma2(acc[2][1], wv1.x, b1);
            ffma2(acc[2][2], wv1.x, b2); ffma2(acc[2][3], wv1.x, b3);
            ffma2(acc[3][0], wv1.y, b0); ffma2(acc[3][1], wv1.y, b1);
            ffma2(acc[3][2], wv1.y, b2); ffma2(acc[3][3], wv1.y, b3);
        }
        __syncthreads();
    }

    // ---- epilogue: relu + vectorized store ----
    const int h = hb + tx * 4;
    if (h < HH) {
        #pragma unroll
        for (int p = 0; p < 4; p++) {
            float2 v0 = unpk(acc[p][0]);
            float2 v1 = unpk(acc[p][1]);
            float2 v2 = unpk(acc[p][2]);
            float2 v3 = unpk(acc[p][3]);
            float4 r0, r1;
            r0.x = fmaxf(v0.x, 0.f); r0.y = fmaxf(v1.x, 0.f);
            r0.z = fmaxf(v2.x, 0.f); r0.w = fmaxf(v3.x, 0.f);
            r1.x = fmaxf(v0.y, 0.f); r1.y = fmaxf(v1.y, 0.f);
            r1.z = fmaxf(v2.y, 0.f); r1.w = fmaxf(v3.y, 0.f);
            int o = o0 + 2 * p;
            *(float4*)(out + (size_t)o * HH + h)       = r0;
            *(float4*)(out + (size_t)(o + 1) * HH + h) = r1;
        }
    }
}

// ---------------------------------------------------------------------------
extern "C" void kernel_launch(void* const* d_in, const int* in_sizes, int n_in,
                              void* d_out, int out_size) {
    const float* x     = (const float*)d_in[0];
    const void*  neigh = d_in[1];
    const float* w     = (const float*)d_in[2];
    float*       out   = (float*)d_out;

    detect_dtype<<<1, 32>>>((const long long*)neigh);
    transpose_x<<<dim3((HH + 31) / 32, C_IN / 32), dim3(32, 8)>>>(x);
    transpose_w<<<(C_OUT * C_IN * KK + 255) / 256, 256>>>(w);
    conv_gemm<<<NBLK, 256>>>(neigh, out);
}

// round 3
// speedup vs baseline: 1.7635x; 1.7635x over previous
#include <cuda_runtime.h>
#include <cuda_bf16.h>
#include <cstdint>

typedef unsigned int u32;
typedef unsigned long long u64;

#define C_IN   64
#define C_OUT  128
#define KK     27
#define HH     100000
#define TILE_H 128
#define NBLK   ((HH + TILE_H - 1) / TILE_H)

// smem tile geometry: rows padded to 144B (9x16B) -> conflict-free ldmatrix
#define ROWB   144
#define TILEB  (128 * ROWB)        // 18432 per operand tile
#define ST_AH  0
#define ST_AL  TILEB
#define ST_BH  (2 * TILEB)
#define ST_BL  (3 * TILEB)
#define STAGE  (4 * TILEB)         // 73728
#define TILES_OFF 14336            // after sIdx (13824B), 1KB-aligned
#define SMEM_BYTES (TILES_OFF + 2 * STAGE)   // 161792

// ---------------- device scratch ----------------
__device__ __nv_bfloat16 g_xhi[(size_t)HH * C_IN];
__device__ __nv_bfloat16 g_xlo[(size_t)HH * C_IN];
__device__ __nv_bfloat16 g_whi[KK * C_OUT * C_IN];   // [k][o][c]
__device__ __nv_bfloat16 g_wlo[KK * C_OUT * C_IN];
__device__ int g_is64;

// ---------------- helpers ----------------
__device__ __forceinline__ u32 smem_u32(const void* p) {
    u32 a;
    asm("{ .reg .u64 t; cvta.to.shared.u64 t, %1; cvt.u32.u64 %0, t; }" : "=r"(a) : "l"(p));
    return a;
}
__device__ __forceinline__ void ldsm4(u32* r, u32 addr) {
    asm volatile("ldmatrix.sync.aligned.m8n8.x4.shared.b16 {%0,%1,%2,%3}, [%4];"
                 : "=r"(r[0]), "=r"(r[1]), "=r"(r[2]), "=r"(r[3]) : "r"(addr));
}
__device__ __forceinline__ void mma16816(float* d, const u32* a, const u32* b) {
    asm volatile("mma.sync.aligned.m16n8k16.row.col.f32.bf16.bf16.f32 "
                 "{%0,%1,%2,%3}, {%4,%5,%6,%7}, {%8,%9}, {%0,%1,%2,%3};"
                 : "+f"(d[0]), "+f"(d[1]), "+f"(d[2]), "+f"(d[3])
                 : "r"(a[0]), "r"(a[1]), "r"(a[2]), "r"(a[3]), "r"(b[0]), "r"(b[1]));
}
#define CP16(dst, src) \
    asm volatile("cp.async.cg.shared.global [%0], [%1], 16;" ::"r"(dst), "l"(src) : "memory")
#define CP16Z(dst, src, sz) \
    asm volatile("cp.async.cg.shared.global [%0], [%1], 16, %2;" ::"r"(dst), "l"(src), "r"(sz) : "memory")
#define CP_COMMIT() asm volatile("cp.async.commit_group;" ::: "memory")
#define CP_WAIT1()  asm volatile("cp.async.wait_group 1;" ::: "memory")

// ---------------- prep kernels ----------------
__global__ void detect_dtype(const long long* __restrict__ n64) {
    if (threadIdx.x == 0 && blockIdx.x == 0) {
        int ok = 1;
        for (int i = 0; i < 256; i++) {
            long long v = n64[i];
            if (v < -(long long)HH || v >= (long long)HH) { ok = 0; break; }
        }
        g_is64 = ok;
    }
}

// x[c*HH + h] -> g_xhi/g_xlo[h*64 + c]  (split transpose)
__global__ void split_x(const float* __restrict__ x) {
    __shared__ float tile[32][33];
    const int hb = blockIdx.x * 32, cb = blockIdx.y * 32;
    const int tx = threadIdx.x, ty = threadIdx.y;
#pragma unroll
    for (int i = 0; i < 32; i += 8) {
        int h = hb + tx;
        tile[ty + i][tx] = (h < HH) ? x[(size_t)(cb + ty + i) * HH + h] : 0.f;
    }
    __syncthreads();
#pragma unroll
    for (int i = 0; i < 32; i += 8) {
        int h = hb + ty + i, c = cb + tx;
        if (h < HH) {
            float v = tile[tx][ty + i];
            __nv_bfloat16 hi = __float2bfloat16(v);
            float r = v - __bfloat162float(hi);
            g_xhi[(size_t)h * C_IN + c] = hi;
            g_xlo[(size_t)h * C_IN + c] = __float2bfloat16(r);
        }
    }
}

// w[o*1728 + c*27 + k] -> g_whi/g_wlo[k*8192 + o*64 + c]
__global__ void split_w(const float* __restrict__ w) {
    int idx = blockIdx.x * blockDim.x + threadIdx.x;
    if (idx >= KK * C_OUT * C_IN) return;
    int k = idx / (C_OUT * C_IN);
    int rem = idx % (C_OUT * C_IN);
    int o = rem / C_IN, c = rem % C_IN;
    float v = w[(size_t)o * (C_IN * KK) + c * KK + k];
    __nv_bfloat16 hi = __float2bfloat16(v);
    float r = v - __bfloat162float(hi);
    g_whi[idx] = hi;
    g_wlo[idx] = __float2bfloat16(r);
}

// ---------------- main kernel ----------------
__global__ __launch_bounds__(256, 1)
void conv_mma(const void* __restrict__ neigh_raw, float* __restrict__ out) {
    extern __shared__ char smem[];
    const u32 sbase = smem_u32(smem);
    int* sIdx = (int*)smem;
    const u32 tiles = sbase + TILES_OFF;

    const int tid = threadIdx.x;
    const int lid = tid & 31, wid = tid >> 5;
    const int wr = wid & 3, wc = wid >> 2;      // warp grid 4(h) x 2(o)
    const int hb = blockIdx.x * TILE_H;

    // ---- stage neighbor indices ----
    {
        const int is64 = g_is64;
        const long long* n64 = (const long long*)neigh_raw;
        const int* n32 = (const int*)neigh_raw;
        for (int j = tid; j < TILE_H * KK; j += 256) {
            int hl = j / KK;
            int n = -1;
            if (hb + hl < HH) {
                size_t gi = (size_t)(hb + hl) * KK + (j % KK);
                long long v = is64 ? n64[gi] : (long long)n32[gi];
                if (v >= 0 && v < HH) n = (int)v;
            }
            sIdx[j] = n;
        }
    }
    __syncthreads();

    // ---- per-thread load roles ----
    const int ar = tid >> 1;           // gather row 0..127
    const int asel = tid & 1;          // 0 = hi, 1 = lo
    const __nv_bfloat16* axsrc = asel ? g_xlo : g_xhi;
    const u32 aoff = (asel ? ST_AL : ST_AH) + ar * ROWB;

    // ---- ldmatrix lane address components ----
    const u32 a_ro = (u32)(lid & 15);
    const u32 a_co = (u32)(lid >> 4);
    const u32 b_ro = (u32)((lid & 7) + ((lid >> 4) << 3));
    const u32 b_co = (u32)((lid >> 3) & 1);

    float acc[2][8][4];
#pragma unroll
    for (int mf = 0; mf < 2; mf++)
#pragma unroll
        for (int nf = 0; nf < 8; nf++)
#pragma unroll
            for (int r = 0; r < 4; r++) acc[mf][nf][r] = 0.f;

    // ---- async load issuer for tap k into buffer buf ----
    auto issue = [&](int k, int buf) {
        const u32 st = tiles + buf * STAGE;
        // A: this thread's gather row (hi or lo), 128B
        int n = sIdx[ar * KK + k];
        const char* src = (const char*)(axsrc + (n < 0 ? 0 : (size_t)n * C_IN));
        u32 sz = (n < 0) ? 0u : 16u;
        u32 dst = st + aoff;
#pragma unroll
        for (int j = 0; j < 8; j++) CP16Z(dst + j * 16, src + j * 16, sz);
        // B: weights hi+lo, linear
        const char* bh = (const char*)(g_whi + (size_t)k * (C_OUT * C_IN));
        const char* bl = (const char*)(g_wlo + (size_t)k * (C_OUT * C_IN));
#pragma unroll
        for (int i = 0; i < 4; i++) {
            int cc = tid + i * 256;            // 0..1023 16B chunks
            int o = cc >> 3, j = cc & 7;
            u32 d = st + ST_BH + o * ROWB + j * 16;
            CP16(d, bh + cc * 16);
            CP16(d + (ST_BL - ST_BH), bl + cc * 16);
        }
    };

    issue(0, 0); CP_COMMIT();
    issue(1, 1); CP_COMMIT();

    for (int k = 0; k < KK; k++) {
        const int buf = k & 1;
        CP_WAIT1();
        __syncthreads();

        const u32 st = tiles + buf * STAGE;
        const u32 aBase = st + ST_AH + (wr * 32 + a_ro) * ROWB + a_co * 16;
        const u32 bBase = st + ST_BH + (wc * 64 + b_ro) * ROWB + b_co * 16;

#pragma unroll
        for (int ks = 0; ks < 4; ks++) {
            u32 ah[2][4], al[2][4], bh[4][4], bl[4][4];
#pragma unroll
            for (int mf = 0; mf < 2; mf++) {
                u32 ad = aBase + mf * (16 * ROWB) + ks * 32;
                ldsm4(ah[mf], ad);
                ldsm4(al[mf], ad + TILEB);
            }
#pragma unroll
            for (int g = 0; g < 4; g++) {
                u32 bd = bBase + g * (16 * ROWB) + ks * 32;
                ldsm4(bh[g], bd);
                ldsm4(bl[g], bd + TILEB);
            }
#pragma unroll
            for (int mf = 0; mf < 2; mf++)
#pragma unroll
                for (int g = 0; g < 4; g++) {
                    mma16816(acc[mf][2 * g],     ah[mf], &bh[g][0]);
                    mma16816(acc[mf][2 * g],     al[mf], &bh[g][0]);
                    mma16816(acc[mf][2 * g],     ah[mf], &bl[g][0]);
                    mma16816(acc[mf][2 * g + 1], ah[mf], &bh[g][2]);
                    mma16816(acc[mf][2 * g + 1], al[mf], &bh[g][2]);
                    mma16816(acc[mf][2 * g + 1], ah[mf], &bl[g][2]);
                }
        }
        __syncthreads();
        if (k + 2 < KK) issue(k + 2, buf);
        CP_COMMIT();
    }

    // ---- epilogue: stage through smem (pitch 132 f32), coalesced f4 stores ----
    float* sC = (float*)(smem + TILES_OFF);
#pragma unroll
    for (int mf = 0; mf < 2; mf++)
#pragma unroll
        for (int nf = 0; nf < 8; nf++)
#pragma unroll
            for (int r = 0; r < 4; r++) {
                int m = wr * 32 + mf * 16 + (lid >> 2) + ((r >> 1) << 3);
                int n = wc * 64 + nf * 8 + ((lid & 3) << 1) + (r & 1);
                sC[n * 132 + m] = fmaxf(acc[mf][nf][r], 0.f);
            }
    __syncthreads();
#pragma unroll
    for (int it = 0; it < 16; it++) {
        int idx = it * 256 + tid;
        int o = idx >> 5, hq = idx & 31;
        int h = hb + hq * 4;
        if (h < HH) {
            float4 v = *(const float4*)(sC + o * 132 + hq * 4);
            *(float4*)(out + (size_t)o * HH + h) = v;
        }
    }
}

// ---------------- launch ----------------
extern "C" void kernel_launch(void* const* d_in, const int* in_sizes, int n_in,
                              void* d_out, int out_size) {
    const float* x = (const float*)d_in[0];
    const void* neigh = d_in[1];
    const float* w = (const float*)d_in[2];
    float* out = (float*)d_out;

    cudaFuncSetAttribute(conv_mma, cudaFuncAttributeMaxDynamicSharedMemorySize, SMEM_BYTES);

    detect_dtype<<<1, 32>>>((const long long*)neigh);
    split_x<<<dim3((HH + 31) / 32, C_IN / 32), dim3(32, 8)>>>(x);
    split_w<<<(KK * C_OUT * C_IN + 255) / 256, 256>>>(w);
    conv_mma<<<NBLK, 256, SMEM_BYTES>>>(neigh, out);
}

// round 4
// speedup vs baseline: 1.8695x; 1.0601x over previous
#include <cuda_runtime.h>
#include <cuda_bf16.h>
#include <cstdint>

typedef unsigned int u32;
typedef unsigned long long u64;

#define C_IN   64
#define C_OUT  128
#define KK     27
#define HH     100000
#define TILE_H 128
#define NBLK   ((HH + TILE_H - 1) / TILE_H)

// smem: 128B rows + SW128 XOR swizzle (conflict-free ldmatrix, no padding)
#define TILEB  16384               // 128 rows x 128 B
#define ST_AH  0
#define ST_AL  TILEB
#define ST_BH  (2 * TILEB)
#define ST_BL  (3 * TILEB)
#define STAGE  (4 * TILEB)         // 65536
#define NSTAGE 3
#define TILES_OFF 14336            // after sIdx (13824 B)
#define SMEM_BYTES (TILES_OFF + NSTAGE * STAGE)   // 210944

#define SWZ(o) ((o) ^ (((o) >> 3) & 0x70))

// ---------------- device scratch ----------------
__device__ __nv_bfloat16 g_xhi[(size_t)HH * C_IN];
__device__ __nv_bfloat16 g_xlo[(size_t)HH * C_IN];
__device__ __nv_bfloat16 g_whi[KK * C_OUT * C_IN];   // [k][o][c]
__device__ __nv_bfloat16 g_wlo[KK * C_OUT * C_IN];
__device__ int g_is64;

// ---------------- helpers ----------------
__device__ __forceinline__ u32 smem_u32(const void* p) {
    u32 a;
    asm("{ .reg .u64 t; cvta.to.shared.u64 t, %1; cvt.u32.u64 %0, t; }" : "=r"(a) : "l"(p));
    return a;
}
__device__ __forceinline__ void ldsm4(u32* r, u32 addr) {
    asm volatile("ldmatrix.sync.aligned.m8n8.x4.shared.b16 {%0,%1,%2,%3}, [%4];"
                 : "=r"(r[0]), "=r"(r[1]), "=r"(r[2]), "=r"(r[3]) : "r"(addr));
}
__device__ __forceinline__ void mma16816(float* d, const u32* a, const u32* b) {
    asm volatile("mma.sync.aligned.m16n8k16.row.col.f32.bf16.bf16.f32 "
                 "{%0,%1,%2,%3}, {%4,%5,%6,%7}, {%8,%9}, {%0,%1,%2,%3};"
                 : "+f"(d[0]), "+f"(d[1]), "+f"(d[2]), "+f"(d[3])
                 : "r"(a[0]), "r"(a[1]), "r"(a[2]), "r"(a[3]), "r"(b[0]), "r"(b[1]));
}
#define CP16(dst, src) \
    asm volatile("cp.async.cg.shared.global [%0], [%1], 16;" ::"r"(dst), "l"(src) : "memory")
#define CP16Z(dst, src, sz) \
    asm volatile("cp.async.cg.shared.global [%0], [%1], 16, %2;" ::"r"(dst), "l"(src), "r"(sz) : "memory")
#define CP_COMMIT() asm volatile("cp.async.commit_group;" ::: "memory")
#define CP_WAIT2()  asm volatile("cp.async.wait_group 2;" ::: "memory")

// ---------------- prep kernels ----------------
__global__ void detect_dtype(const long long* __restrict__ n64) {
    if (threadIdx.x == 0 && blockIdx.x == 0) {
        int ok = 1;
        for (int i = 0; i < 256; i++) {
            long long v = n64[i];
            if (v < -(long long)HH || v >= (long long)HH) { ok = 0; break; }
        }
        g_is64 = ok;
    }
}

__global__ void split_x(const float* __restrict__ x) {
    __shared__ float tile[32][33];
    const int hb = blockIdx.x * 32, cb = blockIdx.y * 32;
    const int tx = threadIdx.x, ty = threadIdx.y;
#pragma unroll
    for (int i = 0; i < 32; i += 8) {
        int h = hb + tx;
        tile[ty + i][tx] = (h < HH) ? x[(size_t)(cb + ty + i) * HH + h] : 0.f;
    }
    __syncthreads();
#pragma unroll
    for (int i = 0; i < 32; i += 8) {
        int h = hb + ty + i, c = cb + tx;
        if (h < HH) {
            float v = tile[tx][ty + i];
            __nv_bfloat16 hi = __float2bfloat16(v);
            float r = v - __bfloat162float(hi);
            g_xhi[(size_t)h * C_IN + c] = hi;
            g_xlo[(size_t)h * C_IN + c] = __float2bfloat16(r);
        }
    }
}

__global__ void split_w(const float* __restrict__ w) {
    int idx = blockIdx.x * blockDim.x + threadIdx.x;
    if (idx >= KK * C_OUT * C_IN) return;
    int k = idx / (C_OUT * C_IN);
    int rem = idx % (C_OUT * C_IN);
    int o = rem / C_IN, c = rem % C_IN;
    float v = w[(size_t)o * (C_IN * KK) + c * KK + k];
    __nv_bfloat16 hi = __float2bfloat16(v);
    float r = v - __bfloat162float(hi);
    g_whi[idx] = hi;
    g_wlo[idx] = __float2bfloat16(r);
}

// ---------------- main kernel ----------------
__global__ __launch_bounds__(256, 1)
void conv_mma(const void* __restrict__ neigh_raw, float* __restrict__ out) {
    extern __shared__ char smem[];
    const u32 sbase = smem_u32(smem);
    int* sIdx = (int*)smem;
    const u32 tiles = sbase + TILES_OFF;

    const int tid = threadIdx.x;
    const int lid = tid & 31, wid = tid >> 5;
    const int wr = wid & 3, wc = wid >> 2;      // warp grid 4(h) x 2(o)
    const int hb = blockIdx.x * TILE_H;

    // ---- stage neighbor indices ----
    {
        const int is64 = g_is64;
        const long long* n64 = (const long long*)neigh_raw;
        const int* n32 = (const int*)neigh_raw;
        for (int j = tid; j < TILE_H * KK; j += 256) {
            int hl = j / KK;
            int n = -1;
            if (hb + hl < HH) {
                size_t gi = (size_t)(hb + hl) * KK + (j % KK);
                long long v = is64 ? n64[gi] : (long long)n32[gi];
                if (v >= 0 && v < HH) n = (int)v;
            }
            sIdx[j] = n;
        }
    }
    __syncthreads();

    // ---- per-thread load roles ----
    const int ar = tid >> 1;           // gather row 0..127
    const int asel = tid & 1;          // 0 = hi, 1 = lo
    const __nv_bfloat16* axsrc = asel ? g_xlo : g_xhi;
    const u32 atile = asel ? ST_AL : ST_AH;

    // ---- ldmatrix lane address components ----
    const u32 a_ro = (u32)(lid & 15);
    const u32 a_co = (u32)(lid >> 4);
    const u32 b_ro = (u32)((lid & 7) + ((lid >> 4) << 3));
    const u32 b_co = (u32)((lid >> 3) & 1);
    const u32 a_row = (u32)(wr * 32) + a_ro;
    const u32 b_row = (u32)(wc * 64) + b_ro;

    float acc[2][8][4];
#pragma unroll
    for (int mf = 0; mf < 2; mf++)
#pragma unroll
        for (int nf = 0; nf < 8; nf++)
#pragma unroll
            for (int r = 0; r < 4; r++) acc[mf][nf][r] = 0.f;

    // ---- async load issuer for tap k into stage st ----
    auto issue = [&](int k, int stg) {
        const u32 st = tiles + stg * STAGE;
        // A: this thread's gather row (hi or lo), 8 x 16B, swizzled
        int n = sIdx[ar * KK + k];
        const char* src = (const char*)(axsrc + (n < 0 ? 0 : (size_t)n * C_IN));
        u32 sz = (n < 0) ? 0u : 16u;
        u32 rowoff = (u32)ar * 128;
#pragma unroll
        for (int j = 0; j < 8; j++)
            CP16Z(st + atile + SWZ(rowoff + j * 16), src + j * 16, sz);
        // B: weights hi+lo, linear 16B chunks, swizzled
        const char* bh = (const char*)(g_whi + (size_t)k * (C_OUT * C_IN));
        const char* bl = (const char*)(g_wlo + (size_t)k * (C_OUT * C_IN));
#pragma unroll
        for (int i = 0; i < 4; i++) {
            int cc = tid + i * 256;            // 0..1023
            u32 d = SWZ((u32)cc * 16);
            CP16(st + ST_BH + d, bh + cc * 16);
            CP16(st + ST_BL + d, bl + cc * 16);
        }
    };

    issue(0, 0); CP_COMMIT();
    issue(1, 1); CP_COMMIT();
    issue(2, 2); CP_COMMIT();

    int stg = 0;
    for (int k = 0; k < KK; k++) {
        CP_WAIT2();
        __syncthreads();

        const u32 st = tiles + stg * STAGE;
#pragma unroll
        for (int ks = 0; ks < 4; ks++) {
            u32 ah[2][4], al[2][4], bh[4][4], bl[4][4];
#pragma unroll
            for (int mf = 0; mf < 2; mf++) {
                u32 off = (a_row + mf * 16) * 128 + (u32)(ks * 32) + a_co * 16;
                u32 ad = st + SWZ(off);
                ldsm4(ah[mf], ad);
                ldsm4(al[mf], ad + TILEB);
            }
#pragma unroll
            for (int g = 0; g < 4; g++) {
                u32 off = (b_row + g * 16) * 128 + (u32)(ks * 32) + b_co * 16;
                u32 bd = st + ST_BH + SWZ(off);
                ldsm4(bh[g], bd);
                ldsm4(bl[g], bd + TILEB);
            }
#pragma unroll
            for (int mf = 0; mf < 2; mf++)
#pragma unroll
                for (int g = 0; g < 4; g++) {
                    mma16816(acc[mf][2 * g],     ah[mf], &bh[g][0]);
                    mma16816(acc[mf][2 * g + 1], ah[mf], &bh[g][2]);
                    mma16816(acc[mf][2 * g],     al[mf], &bh[g][0]);
                    mma16816(acc[mf][2 * g + 1], al[mf], &bh[g][2]);
                    mma16816(acc[mf][2 * g],     ah[mf], &bl[g][0]);
                    mma16816(acc[mf][2 * g + 1], ah[mf], &bl[g][2]);
                }
        }
        __syncthreads();
        if (k + 3 < KK) issue(k + 3, stg);
        CP_COMMIT();
        stg = (stg == NSTAGE - 1) ? 0 : stg + 1;
    }

    // ---- epilogue: stage through smem (pitch 132 f32), coalesced f4 stores ----
    float* sC = (float*)(smem + TILES_OFF);
#pragma unroll
    for (int mf = 0; mf < 2; mf++)
#pragma unroll
        for (int nf = 0; nf < 8; nf++)
#pragma unroll
            for (int r = 0; r < 4; r++) {
                int m = wr * 32 + mf * 16 + (lid >> 2) + ((r >> 1) << 3);
                int n = wc * 64 + nf * 8 + ((lid & 3) << 1) + (r & 1);
                sC[n * 132 + m] = fmaxf(acc[mf][nf][r], 0.f);
            }
    __syncthreads();
#pragma unroll
    for (int it = 0; it < 16; it++) {
        int idx = it * 256 + tid;
        int o = idx >> 5, hq = idx & 31;
        int h = hb + hq * 4;
        if (h < HH) {
            float4 v = *(const float4*)(sC + o * 132 + hq * 4);
            *(float4*)(out + (size_t)o * HH + h) = v;
        }
    }
}

// ---------------- launch ----------------
extern "C" void kernel_launch(void* const* d_in, const int* in_sizes, int n_in,
                              void* d_out, int out_size) {
    const float* x = (const float*)d_in[0];
    const void* neigh = d_in[1];
    const float* w = (const float*)d_in[2];
    float* out = (float*)d_out;

    cudaFuncSetAttribute(conv_mma, cudaFuncAttributeMaxDynamicSharedMemorySize, SMEM_BYTES);

    detect_dtype<<<1, 32>>>((const long long*)neigh);
    split_x<<<dim3((HH + 31) / 32, C_IN / 32), dim3(32, 8)>>>(x);
    split_w<<<(KK * C_OUT * C_IN + 255) / 256, 256>>>(w);
    conv_mma<<<NBLK, 256, SMEM_BYTES>>>(neigh, out);
}

// round 5
// speedup vs baseline: 2.2570x; 1.2073x over previous
#include <cuda_runtime.h>
#include <cuda_bf16.h>
#include <cstdint>

typedef unsigned int u32;
typedef unsigned long long u64;

#define C_IN   64
#define C_OUT  128
#define KK     27
#define HH     100000
#define TILE_H 128
#define NBLK   ((HH + TILE_H - 1) / TILE_H)
#define NTHR   512

// smem: 128B rows + SW128 XOR swizzle (conflict-free ldmatrix)
#define TILEB  16384               // 128 rows x 128 B
#define ST_AH  0
#define ST_AL  TILEB
#define ST_BH  (2 * TILEB)
#define ST_BL  (3 * TILEB)
#define STAGE  (4 * TILEB)         // 65536
#define NSTAGE 3
#define TILES_OFF 14336            // after sIdx (13824 B)
#define SMEM_BYTES (TILES_OFF + NSTAGE * STAGE)   // 210944

#define SWZ(o) ((o) ^ (((o) >> 3) & 0x70))

// ---------------- device scratch ----------------
__device__ __nv_bfloat16 g_xhi[(size_t)HH * C_IN];
__device__ __nv_bfloat16 g_xlo[(size_t)HH * C_IN];
__device__ __nv_bfloat16 g_whi[KK * C_OUT * C_IN];   // [k][o][c]
__device__ __nv_bfloat16 g_wlo[KK * C_OUT * C_IN];
__device__ int g_is64;

// ---------------- helpers ----------------
__device__ __forceinline__ u32 smem_u32(const void* p) {
    u32 a;
    asm("{ .reg .u64 t; cvta.to.shared.u64 t, %1; cvt.u32.u64 %0, t; }" : "=r"(a) : "l"(p));
    return a;
}
__device__ __forceinline__ void ldsm4(u32* r, u32 addr) {
    asm volatile("ldmatrix.sync.aligned.m8n8.x4.shared.b16 {%0,%1,%2,%3}, [%4];"
                 : "=r"(r[0]), "=r"(r[1]), "=r"(r[2]), "=r"(r[3]) : "r"(addr));
}
__device__ __forceinline__ void mma16816(float* d, const u32* a, const u32* b) {
    asm volatile("mma.sync.aligned.m16n8k16.row.col.f32.bf16.bf16.f32 "
                 "{%0,%1,%2,%3}, {%4,%5,%6,%7}, {%8,%9}, {%0,%1,%2,%3};"
                 : "+f"(d[0]), "+f"(d[1]), "+f"(d[2]), "+f"(d[3])
                 : "r"(a[0]), "r"(a[1]), "r"(a[2]), "r"(a[3]), "r"(b[0]), "r"(b[1]));
}
#define CP16(dst, src) \
    asm volatile("cp.async.cg.shared.global [%0], [%1], 16;" ::"r"(dst), "l"(src) : "memory")
#define CP16Z(dst, src, sz) \
    asm volatile("cp.async.cg.shared.global [%0], [%1], 16, %2;" ::"r"(dst), "l"(src), "r"(sz) : "memory")
#define CP_COMMIT() asm volatile("cp.async.commit_group;" ::: "memory")
#define CP_WAIT2()  asm volatile("cp.async.wait_group 2;" ::: "memory")

// ---------------- prep kernels ----------------
__global__ void detect_dtype(const long long* __restrict__ n64) {
    if (threadIdx.x == 0 && blockIdx.x == 0) {
        int ok = 1;
        for (int i = 0; i < 256; i++) {
            long long v = n64[i];
            if (v < -(long long)HH || v >= (long long)HH) { ok = 0; break; }
        }
        g_is64 = ok;
    }
}

__global__ void split_x(const float* __restrict__ x) {
    __shared__ float tile[32][33];
    const int hb = blockIdx.x * 32, cb = blockIdx.y * 32;
    const int tx = threadIdx.x, ty = threadIdx.y;
#pragma unroll
    for (int i = 0; i < 32; i += 8) {
        int h = hb + tx;
        tile[ty + i][tx] = (h < HH) ? x[(size_t)(cb + ty + i) * HH + h] : 0.f;
    }
    __syncthreads();
#pragma unroll
    for (int i = 0; i < 32; i += 8) {
        int h = hb + ty + i, c = cb + tx;
        if (h < HH) {
            float v = tile[tx][ty + i];
            __nv_bfloat16 hi = __float2bfloat16(v);
            float r = v - __bfloat162float(hi);
            g_xhi[(size_t)h * C_IN + c] = hi;
            g_xlo[(size_t)h * C_IN + c] = __float2bfloat16(r);
        }
    }
}

__global__ void split_w(const float* __restrict__ w) {
    int idx = blockIdx.x * blockDim.x + threadIdx.x;
    if (idx >= KK * C_OUT * C_IN) return;
    int k = idx / (C_OUT * C_IN);
    int rem = idx % (C_OUT * C_IN);
    int o = rem / C_IN, c = rem % C_IN;
    float v = w[(size_t)o * (C_IN * KK) + c * KK + k];
    __nv_bfloat16 hi = __float2bfloat16(v);
    float r = v - __bfloat162float(hi);
    g_whi[idx] = hi;
    g_wlo[idx] = __float2bfloat16(r);
}

// ---------------- main kernel ----------------
__global__ __launch_bounds__(NTHR, 1)
void conv_mma(const void* __restrict__ neigh_raw, float* __restrict__ out) {
    extern __shared__ char smem[];
    const u32 sbase = smem_u32(smem);
    int* sIdx = (int*)smem;
    const u32 tiles = sbase + TILES_OFF;

    const int tid = threadIdx.x;
    const int lid = tid & 31, wid = tid >> 5;    // 16 warps
    const int wr = wid & 3, wc = wid >> 2;       // warp grid 4(h) x 4(o)
    const int hb = blockIdx.x * TILE_H;

    // ---- stage neighbor indices ----
    {
        const int is64 = g_is64;
        const long long* n64 = (const long long*)neigh_raw;
        const int* n32 = (const int*)neigh_raw;
        for (int j = tid; j < TILE_H * KK; j += NTHR) {
            int hl = j / KK;
            int n = -1;
            if (hb + hl < HH) {
                size_t gi = (size_t)(hb + hl) * KK + (j % KK);
                long long v = is64 ? n64[gi] : (long long)n32[gi];
                if (v >= 0 && v < HH) n = (int)v;
            }
            sIdx[j] = n;
        }
    }
    __syncthreads();

    // ---- per-thread load roles: A = (row, half, 4-chunk group) ----
    const int ar   = tid >> 2;                 // 0..127
    const int asel = (tid >> 1) & 1;           // 0 = hi, 1 = lo
    const int jgrp = (tid & 1) * 4;            // chunk group 0..3 / 4..7
    const __nv_bfloat16* axsrc = asel ? g_xlo : g_xhi;
    const u32 atile = asel ? ST_AL : ST_AH;

    // ---- ldmatrix lane address components ----
    const u32 a_ro = (u32)(lid & 15);
    const u32 a_co = (u32)(lid >> 4);
    const u32 b_ro = (u32)((lid & 7) + ((lid >> 4) << 3));
    const u32 b_co = (u32)((lid >> 3) & 1);
    const u32 a_row = (u32)(wr * 32) + a_ro;
    const u32 b_row = (u32)(wc * 32) + b_ro;

    float acc[2][4][4];
#pragma unroll
    for (int mf = 0; mf < 2; mf++)
#pragma unroll
        for (int nf = 0; nf < 4; nf++)
#pragma unroll
            for (int r = 0; r < 4; r++) acc[mf][nf][r] = 0.f;

    // ---- async load issuer for tap k into stage stg ----
    auto issue = [&](int k, int stg) {
        const u32 st = tiles + stg * STAGE;
        // A: 4 x 16B of this (row, half)
        int n = sIdx[ar * KK + k];
        const char* src = (const char*)(axsrc + (n < 0 ? 0 : (size_t)n * C_IN)) + jgrp * 16;
        u32 sz = (n < 0) ? 0u : 16u;
        u32 rowoff = (u32)ar * 128 + (u32)jgrp * 16;
#pragma unroll
        for (int j = 0; j < 4; j++)
            CP16Z(st + atile + SWZ(rowoff + j * 16), src + j * 16, sz);
        // B: weights hi+lo, 2 chunks each
        const char* bh = (const char*)(g_whi + (size_t)k * (C_OUT * C_IN));
        const char* bl = (const char*)(g_wlo + (size_t)k * (C_OUT * C_IN));
#pragma unroll
        for (int i = 0; i < 2; i++) {
            int cc = tid + i * NTHR;           // 0..1023
            u32 d = SWZ((u32)cc * 16);
            CP16(st + ST_BH + d, bh + cc * 16);
            CP16(st + ST_BL + d, bl + cc * 16);
        }
    };

    issue(0, 0); CP_COMMIT();
    issue(1, 1); CP_COMMIT();
    issue(2, 2); CP_COMMIT();

    int stg = 0;
    for (int k = 0; k < KK; k++) {
        CP_WAIT2();
        __syncthreads();

        const u32 st = tiles + stg * STAGE;
#pragma unroll
        for (int ks = 0; ks < 4; ks++) {
            u32 ah[2][4], al[2][4], bh[2][4], bl[2][4];
#pragma unroll
            for (int mf = 0; mf < 2; mf++) {
                u32 off = (a_row + mf * 16) * 128 + (u32)(ks * 32) + a_co * 16;
                u32 ad = st + SWZ(off);
                ldsm4(ah[mf], ad);
                ldsm4(al[mf], ad + TILEB);
            }
#pragma unroll
            for (int g = 0; g < 2; g++) {
                u32 off = (b_row + g * 16) * 128 + (u32)(ks * 32) + b_co * 16;
                u32 bd = st + ST_BH + SWZ(off);
                ldsm4(bh[g], bd);
                ldsm4(bl[g], bd + TILEB);
            }
#pragma unroll
            for (int mf = 0; mf < 2; mf++)
#pragma unroll
                for (int g = 0; g < 2; g++) {
                    mma16816(acc[mf][2 * g],     ah[mf], &bh[g][0]);
                    mma16816(acc[mf][2 * g + 1], ah[mf], &bh[g][2]);
                    mma16816(acc[mf][2 * g],     al[mf], &bh[g][0]);
                    mma16816(acc[mf][2 * g + 1], al[mf], &bh[g][2]);
                    mma16816(acc[mf][2 * g],     ah[mf], &bl[g][0]);
                    mma16816(acc[mf][2 * g + 1], ah[mf], &bl[g][2]);
                }
        }
        __syncthreads();
        if (k + 3 < KK) issue(k + 3, stg);
        CP_COMMIT();
        stg = (stg == NSTAGE - 1) ? 0 : stg + 1;
    }

    // ---- epilogue: stage through smem (pitch 132 f32), coalesced f4 stores ----
    float* sC = (float*)(smem + TILES_OFF);
#pragma unroll
    for (int mf = 0; mf < 2; mf++)
#pragma unroll
        for (int nf = 0; nf < 4; nf++)
#pragma unroll
            for (int r = 0; r < 4; r++) {
                int m = wr * 32 + mf * 16 + (lid >> 2) + ((r >> 1) << 3);
                int n = wc * 32 + nf * 8 + ((lid & 3) << 1) + (r & 1);
                sC[n * 132 + m] = fmaxf(acc[mf][nf][r], 0.f);
            }
    __syncthreads();
#pragma unroll
    for (int it = 0; it < 8; it++) {
        int idx = it * NTHR + tid;
        int o = idx >> 5, hq = idx & 31;
        int h = hb + hq * 4;
        if (h < HH) {
            float4 v = *(const float4*)(sC + o * 132 + hq * 4);
            *(float4*)(out + (size_t)o * HH + h) = v;
        }
    }
}

// ---------------- launch ----------------
extern "C" void kernel_launch(void* const* d_in, const int* in_sizes, int n_in,
                              void* d_out, int out_size) {
    const float* x = (const float*)d_in[0];
    const void* neigh = d_in[1];
    const float* w = (const float*)d_in[2];
    float* out = (float*)d_out;

    cudaFuncSetAttribute(conv_mma, cudaFuncAttributeMaxDynamicSharedMemorySize, SMEM_BYTES);

    detect_dtype<<<1, 32>>>((const long long*)neigh);
    split_x<<<dim3((HH + 31) / 32, C_IN / 32), dim3(32, 8)>>>(x);
    split_w<<<(KK * C_OUT * C_IN + 255) / 256, 256>>>(w);
    conv_mma<<<NBLK, NTHR, SMEM_BYTES>>>(neigh, out);
}